// round 1
// baseline (speedup 1.0000x reference)
#include <cuda_runtime.h>

// ---------------- problem constants ----------------
#define Bb 4
#define NN 1024
#define DIMV 1024
#define HH 16
#define DHd 64
#define VOC 129            // 2*MAXREL+1
#define MAXREL 64
#define TOPKv 256
#define BHH (Bb*HH)        // 64
#define ROWS (BHH*NN)      // 65536
#define SCALEv 0.125f      // DH^-0.5

// ---------------- device scratch (no allocs allowed) ----------------
__device__ float g_Q[ROWS*DHd];
__device__ float g_K[ROWS*DHd];
__device__ float g_V[ROWS*DHd];
__device__ float g_S[(size_t)ROWS*NN];        // 256 MB scores
__device__ float g_QR[ROWS*VOC];              // q @ rel_k_emb^T
__device__ float g_CW[ROWS*TOPKv];            // compact attn weights
__device__ int   g_CI[ROWS*TOPKv];            // compact attn column indices
__device__ float g_ARel[ROWS*DHd];            // attn @ rel_v
__device__ float g_VA[ROWS*DHd];
__device__ float g_VB[ROWS*DHd];
__device__ float g_Res[ROWS*DHd];

// =====================================================================
// Kernel 1: qkv = x @ Wqkv^T + bqkv, scattered into per-head Q/K/V
// M=4096, C=3072, K=1024. 64x64 tile, BK=16, 256 threads, 4x4/thread.
// =====================================================================
__global__ void k_gemm_qkv(const float* __restrict__ X,
                           const float* __restrict__ W,
                           const float* __restrict__ bias) {
    __shared__ float As[16][72];
    __shared__ float Bs[16][72];
    int tx = threadIdx.x, ty = threadIdx.y;
    int tid = ty * 16 + tx;
    int m0 = blockIdx.y * 64, c0 = blockIdx.x * 64;
    int lr = tid >> 2;           // 0..63
    int lk = (tid & 3) * 4;      // 0,4,8,12
    float acc[4][4] = {};

    for (int k0 = 0; k0 < DIMV; k0 += 16) {
        float4 av = *(const float4*)&X[(size_t)(m0 + lr) * DIMV + k0 + lk];
        float4 bv = *(const float4*)&W[(size_t)(c0 + lr) * DIMV + k0 + lk];
        As[lk+0][lr] = av.x; As[lk+1][lr] = av.y; As[lk+2][lr] = av.z; As[lk+3][lr] = av.w;
        Bs[lk+0][lr] = bv.x; Bs[lk+1][lr] = bv.y; Bs[lk+2][lr] = bv.z; Bs[lk+3][lr] = bv.w;
        __syncthreads();
        #pragma unroll
        for (int k = 0; k < 16; k++) {
            float4 a = *(const float4*)&As[k][ty * 4];
            float4 b = *(const float4*)&Bs[k][tx * 4];
            acc[0][0] += a.x*b.x; acc[0][1] += a.x*b.y; acc[0][2] += a.x*b.z; acc[0][3] += a.x*b.w;
            acc[1][0] += a.y*b.x; acc[1][1] += a.y*b.y; acc[1][2] += a.y*b.z; acc[1][3] += a.y*b.w;
            acc[2][0] += a.z*b.x; acc[2][1] += a.z*b.y; acc[2][2] += a.z*b.z; acc[2][3] += a.z*b.w;
            acc[3][0] += a.w*b.x; acc[3][1] += a.w*b.y; acc[3][2] += a.w*b.z; acc[3][3] += a.w*b.w;
        }
        __syncthreads();
    }
    #pragma unroll
    for (int i = 0; i < 4; i++) {
        int m = m0 + ty * 4 + i;
        int b = m >> 10, n = m & 1023;
        #pragma unroll
        for (int j = 0; j < 4; j++) {
            int c = c0 + tx * 4 + j;
            float v = acc[i][j] + bias[c];
            int part = c >> 10;
            int hc = c & 1023;
            int h = hc >> 6, dh = hc & 63;
            float* dst = (part == 0) ? g_Q : ((part == 1) ? g_K : g_V);
            dst[((size_t)((b * HH + h) * NN + n)) * DHd + dh] = v;
        }
    }
}

// =====================================================================
// Kernel 2: QR[row][t] = Q[row] . rel_k_emb[t]   (row in 0..ROWS)
// =====================================================================
__global__ void k_qr(const float* __restrict__ relk) {
    __shared__ float sQ[32][65];
    int tid = threadIdx.x;
    int row0 = blockIdx.x * 32;
    for (int e = tid; e < 32 * 64; e += 256) {
        int r = e >> 6, d = e & 63;
        sQ[r][d] = g_Q[(size_t)(row0 + r) * DHd + d];
    }
    __syncthreads();
    for (int task = tid; task < 32 * VOC; task += 256) {
        int r = task / VOC, t = task % VOC;
        const float* rk = &relk[t * DHd];
        float acc = 0.f;
        #pragma unroll
        for (int d = 0; d < 64; d++) acc += sQ[r][d] * __ldg(&rk[d]);
        g_QR[(size_t)(row0 + r) * VOC + t] = acc;
    }
}

// =====================================================================
// Kernel 3: S[bh][i][j] = SCALE * Q[i].K[j] + QR[i][clip(i-j)+64]
// grid (16,16,64), 64x64 tile, full K=64 in smem.
// =====================================================================
__global__ void k_scores() {
    __shared__ float Qs[64][72];   // [d][i]
    __shared__ float Ks[64][72];   // [d][j]
    int tx = threadIdx.x, ty = threadIdx.y;
    int tid = ty * 16 + tx;
    int bh = blockIdx.z;
    int i0 = blockIdx.y * 64, j0 = blockIdx.x * 64;
    int lr = tid >> 2;
    int lk = (tid & 3) * 4;
    size_t qbase = (size_t)(bh * NN + i0) * DHd;
    size_t kbase = (size_t)(bh * NN + j0) * DHd;
    #pragma unroll
    for (int rep = 0; rep < 4; rep++) {
        int d = rep * 16 + lk;
        float4 qv = *(const float4*)&g_Q[qbase + (size_t)lr * DHd + d];
        float4 kv = *(const float4*)&g_K[kbase + (size_t)lr * DHd + d];
        Qs[d+0][lr] = qv.x; Qs[d+1][lr] = qv.y; Qs[d+2][lr] = qv.z; Qs[d+3][lr] = qv.w;
        Ks[d+0][lr] = kv.x; Ks[d+1][lr] = kv.y; Ks[d+2][lr] = kv.z; Ks[d+3][lr] = kv.w;
    }
    __syncthreads();
    float acc[4][4] = {};
    #pragma unroll 16
    for (int d = 0; d < 64; d++) {
        float4 a = *(const float4*)&Qs[d][ty * 4];
        float4 b = *(const float4*)&Ks[d][tx * 4];
        acc[0][0] += a.x*b.x; acc[0][1] += a.x*b.y; acc[0][2] += a.x*b.z; acc[0][3] += a.x*b.w;
        acc[1][0] += a.y*b.x; acc[1][1] += a.y*b.y; acc[1][2] += a.y*b.z; acc[1][3] += a.y*b.w;
        acc[2][0] += a.z*b.x; acc[2][1] += a.z*b.y; acc[2][2] += a.z*b.z; acc[2][3] += a.z*b.w;
        acc[3][0] += a.w*b.x; acc[3][1] += a.w*b.y; acc[3][2] += a.w*b.z; acc[3][3] += a.w*b.w;
    }
    #pragma unroll
    for (int i = 0; i < 4; i++) {
        int ii = i0 + ty * 4 + i;
        const float* qr = &g_QR[(size_t)(bh * NN + ii) * VOC];
        size_t sbase = ((size_t)(bh * NN + ii)) * NN;
        #pragma unroll
        for (int j = 0; j < 4; j++) {
            int jj = j0 + tx * 4 + j;
            int d = ii - jj;
            d = d < -MAXREL ? -MAXREL : (d > MAXREL ? MAXREL : d);
            g_S[sbase + jj] = acc[i][j] * SCALEv + qr[d + MAXREL];
        }
    }
}

// float <-> order-preserving uint key
__device__ __forceinline__ unsigned ftokey(float f) {
    unsigned u = __float_as_uint(f);
    return (u & 0x80000000u) ? ~u : (u | 0x80000000u);
}
__device__ __forceinline__ float keytof(unsigned u) {
    return (u & 0x80000000u) ? __uint_as_float(u ^ 0x80000000u) : __uint_as_float(~u);
}

// =====================================================================
// Kernel 4 (fused): per-row exact top-256 threshold (bitonic sort of keys)
// + masked softmax + deterministic compaction (prefix scan)
// + rel_v bucket trick -> ARel.   One block per score row.
// =====================================================================
__global__ void k_select(const float* __restrict__ relv) {
    __shared__ float sbuf[1024];
    __shared__ unsigned key[1024];
    __shared__ float redA[256];
    __shared__ float redB[256];
    __shared__ float rbin[VOC];
    __shared__ int scanA[256];

    int row = blockIdx.x;
    int tid = threadIdx.x;
    int i = row & (NN - 1);
    const float* src = &g_S[(size_t)row * NN];

    float lv[4];
    #pragma unroll
    for (int r = 0; r < 4; r++) {
        int j = tid * 4 + r;
        lv[r] = src[j];
        sbuf[j] = lv[r];
        key[j] = ftokey(lv[r]);
    }
    __syncthreads();

    // bitonic sort ascending (1024 elems, 256 threads)
    for (int k = 2; k <= 1024; k <<= 1) {
        for (int j = k >> 1; j > 0; j >>= 1) {
            for (int idx = tid; idx < 1024; idx += 256) {
                int ixj = idx ^ j;
                if (ixj > idx) {
                    unsigned a = key[idx], b = key[ixj];
                    bool up = ((idx & k) == 0);
                    if ((a > b) == up) { key[idx] = b; key[ixj] = a; }
                }
            }
            __syncthreads();
        }
    }
    float thr  = keytof(key[1024 - TOPKv]);  // 256th largest (kept: s >= thr)
    float rmax = keytof(key[1023]);          // row max (always kept)
    __syncthreads();

    // masked exp; marker -1 for masked-out
    float lsum = 0.f;
    #pragma unroll
    for (int r = 0; r < 4; r++) {
        int j = tid * 4 + r;
        float e;
        if (lv[r] >= thr) { e = __expf(lv[r] - rmax); lsum += e; }
        else e = -1.0f;
        sbuf[j] = e;
    }
    redA[tid] = lsum;
    __syncthreads();
    for (int s = 128; s > 0; s >>= 1) {
        if (tid < s) redA[tid] += redA[tid + s];
        __syncthreads();
    }
    float inv = 1.0f / redA[0];
    __syncthreads();

    // rel_v buckets: t in 1..127 are single elements j = i+64-t;
    // t=0 sums j>=i+64, t=128 sums j<=i-64 (deterministic tree reduce)
    if (tid >= 1 && tid < 128) {
        int j = i + MAXREL - tid;
        float v = 0.f;
        if (j >= 0 && j < NN) {
            float e = sbuf[j];
            if (e >= 0.f) v = e * inv;
        }
        rbin[tid] = v;
    }
    float s0 = 0.f, s128 = 0.f;
    #pragma unroll
    for (int r = 0; r < 4; r++) {
        int j = tid * 4 + r;
        float e = sbuf[j];
        float a = (e >= 0.f) ? e * inv : 0.f;
        if (j >= i + MAXREL) s0 += a;
        if (j <= i - MAXREL) s128 += a;
    }
    redA[tid] = s0; redB[tid] = s128;
    __syncthreads();
    for (int s = 128; s > 0; s >>= 1) {
        if (tid < s) { redA[tid] += redA[tid + s]; redB[tid] += redB[tid + s]; }
        __syncthreads();
    }
    if (tid == 0) { rbin[0] = redA[0]; rbin[MAXREL * 2] = redB[0]; }
    __syncthreads();

    if (tid < DHd) {
        float acc = 0.f;
        #pragma unroll
        for (int t = 0; t < VOC; t++) acc += rbin[t] * __ldg(&relv[t * DHd + tid]);
        g_ARel[(size_t)row * DHd + tid] = acc;
    }

    // deterministic compaction (source order) into CI/CW
    int kc = 0;
    #pragma unroll
    for (int r = 0; r < 4; r++) if (sbuf[tid * 4 + r] >= 0.f) kc++;
    scanA[tid] = kc;
    __syncthreads();
    for (int off = 1; off < 256; off <<= 1) {
        int v = (tid >= off) ? scanA[tid - off] : 0;
        __syncthreads();
        scanA[tid] += v;
        __syncthreads();
    }
    int pos = scanA[tid] - kc;
    size_t cbase = (size_t)row * TOPKv;
    #pragma unroll
    for (int r = 0; r < 4; r++) {
        int j = tid * 4 + r;
        float e = sbuf[j];
        if (e >= 0.f) {
            if (pos < TOPKv) { g_CI[cbase + pos] = j; g_CW[cbase + pos] = e * inv; }
            pos++;
        }
    }
}

// =====================================================================
// Kernel 5: sparse apply v_out = attn @ v_in (+ARel on ord 0),
// Res (+)= sigmoid(alpha)*v_out. Blocks: (bh, d-half). V half staged in smem.
// =====================================================================
__global__ void k_apply(int ord, const float* __restrict__ alphas_raw) {
    extern __shared__ float smem[];
    float*  sV  = smem;                         // 1024*32 floats = 128 KB
    float2* sIW = (float2*)(smem + 1024 * 32);  // 8 warps * 256 = 16 KB

    const float* Vin  = (ord == 0) ? g_V  : ((ord == 1) ? g_VA : g_VB);
    float*       Vout = (ord == 0) ? g_VA : ((ord == 1) ? g_VB : g_VA);

    int bh = blockIdx.x >> 1;
    int d0 = (blockIdx.x & 1) * 32;
    int tid = threadIdx.x, wid = tid >> 5, lane = tid & 31;
    size_t vbase = (size_t)bh * NN * DHd;

    for (int e = tid; e < 1024 * 32; e += 256) {
        int r = e >> 5, c = e & 31;
        sV[e] = Vin[vbase + (size_t)r * DHd + d0 + c];
    }
    __syncthreads();

    int h = bh & (HH - 1);
    float araw = alphas_raw[ord * HH + h];
    float alpha = 1.0f / (1.0f + __expf(-araw));
    float2* myIW = sIW + wid * 256;

    for (int i = wid; i < NN; i += 8) {
        int row = bh * NN + i;
        const int*   ci = &g_CI[(size_t)row * TOPKv];
        const float* cw = &g_CW[(size_t)row * TOPKv];
        #pragma unroll
        for (int q = 0; q < 8; q++) {
            int p = q * 32 + lane;
            myIW[p] = make_float2(cw[p], __int_as_float(ci[p]));
        }
        __syncwarp();
        float acc = 0.f;
        #pragma unroll 8
        for (int p = 0; p < TOPKv; p++) {
            float2 iw = myIW[p];
            int idx = __float_as_int(iw.y);
            acc += iw.x * sV[idx * 32 + lane];
        }
        __syncwarp();
        size_t oidx = (size_t)row * DHd + d0 + lane;
        if (ord == 0) acc += g_ARel[oidx];
        Vout[oidx] = acc;
        float rv = alpha * acc;
        if (ord == 0) g_Res[oidx] = rv;
        else          g_Res[oidx] += rv;
    }
}

// =====================================================================
// Kernel 6: out = res_flat @ Wout^T + bout.  M=4096, O=1024, K=1024.
// A gathered from g_Res head layout.
// =====================================================================
__global__ void k_gemm_out(const float* __restrict__ W,
                           const float* __restrict__ bias,
                           float* __restrict__ out) {
    __shared__ float As[16][72];
    __shared__ float Bs[16][72];
    int tx = threadIdx.x, ty = threadIdx.y;
    int tid = ty * 16 + tx;
    int m0 = blockIdx.y * 64, o0 = blockIdx.x * 64;
    int lr = tid >> 2;
    int lk = (tid & 3) * 4;
    float acc[4][4] = {};

    for (int k0 = 0; k0 < DIMV; k0 += 16) {
        int k = k0 + lk;
        int m = m0 + lr;
        int b = m >> 10, n = m & 1023;
        int hh = k >> 6, dh = k & 63;
        float4 av = *(const float4*)&g_Res[((size_t)((b * HH + hh) * NN + n)) * DHd + dh];
        float4 bv = *(const float4*)&W[(size_t)(o0 + lr) * DIMV + k];
        As[lk+0][lr] = av.x; As[lk+1][lr] = av.y; As[lk+2][lr] = av.z; As[lk+3][lr] = av.w;
        Bs[lk+0][lr] = bv.x; Bs[lk+1][lr] = bv.y; Bs[lk+2][lr] = bv.z; Bs[lk+3][lr] = bv.w;
        __syncthreads();
        #pragma unroll
        for (int kk = 0; kk < 16; kk++) {
            float4 a = *(const float4*)&As[kk][ty * 4];
            float4 b = *(const float4*)&Bs[kk][tx * 4];
            acc[0][0] += a.x*b.x; acc[0][1] += a.x*b.y; acc[0][2] += a.x*b.z; acc[0][3] += a.x*b.w;
            acc[1][0] += a.y*b.x; acc[1][1] += a.y*b.y; acc[1][2] += a.y*b.z; acc[1][3] += a.y*b.w;
            acc[2][0] += a.z*b.x; acc[2][1] += a.z*b.y; acc[2][2] += a.z*b.z; acc[2][3] += a.z*b.w;
            acc[3][0] += a.w*b.x; acc[3][1] += a.w*b.y; acc[3][2] += a.w*b.z; acc[3][3] += a.w*b.w;
        }
        __syncthreads();
    }
    #pragma unroll
    for (int i = 0; i < 4; i++) {
        int m = m0 + ty * 4 + i;
        #pragma unroll
        for (int j = 0; j < 4; j++) {
            int o = o0 + tx * 4 + j;
            out[(size_t)m * DIMV + o] = acc[i][j] + bias[o];
        }
    }
}

// =====================================================================
extern "C" void kernel_launch(void* const* d_in, const int* in_sizes, int n_in,
                              void* d_out, int out_size) {
    const float* x      = (const float*)d_in[0];
    const float* Wqkv   = (const float*)d_in[1];
    const float* bqkv   = (const float*)d_in[2];
    const float* Wout   = (const float*)d_in[3];
    const float* bout   = (const float*)d_in[4];
    const float* relk   = (const float*)d_in[5];
    const float* relv   = (const float*)d_in[6];
    const float* alphas = (const float*)d_in[7];
    float* out = (float*)d_out;

    k_gemm_qkv<<<dim3(48, 64), dim3(16, 16)>>>(x, Wqkv, bqkv);
    k_qr<<<ROWS / 32, 256>>>(relk);
    k_scores<<<dim3(16, 16, BHH), dim3(16, 16)>>>();
    k_select<<<ROWS, 256>>>(relv);

    cudaFuncSetAttribute(k_apply, cudaFuncAttributeMaxDynamicSharedMemorySize, 147456);
    k_apply<<<BHH * 2, 256, 147456>>>(0, alphas);
    k_apply<<<BHH * 2, 256, 147456>>>(1, alphas);
    k_apply<<<BHH * 2, 256, 147456>>>(2, alphas);

    k_gemm_out<<<dim3(16, 64), dim3(16, 16)>>>(Wout, bout, out);
}

// round 2
// speedup vs baseline: 1.5036x; 1.5036x over previous
#include <cuda_runtime.h>

// ---------------- problem constants ----------------
#define Bb 4
#define NN 1024
#define DIMV 1024
#define HH 16
#define DHd 64
#define VOC 129            // 2*MAXREL+1
#define MAXREL 64
#define TOPKv 256
#define BHH (Bb*HH)        // 64
#define ROWS (BHH*NN)      // 65536
#define SCALEv 0.125f      // DH^-0.5

// ---------------- device scratch (no allocs allowed) ----------------
__device__ float g_Q[ROWS*DHd];
__device__ float g_K[ROWS*DHd];
__device__ float g_V[ROWS*DHd];
__device__ float g_S[(size_t)ROWS*NN];        // 256 MB scores
__device__ float g_QR[ROWS*VOC];              // q @ rel_k_emb^T
__device__ float g_CW[ROWS*TOPKv];            // compact attn weights
__device__ int   g_CI[ROWS*TOPKv];            // compact attn column indices
__device__ float g_ARel[ROWS*DHd];            // attn @ rel_v
__device__ float g_VA[ROWS*DHd];
__device__ float g_VB[ROWS*DHd];
__device__ float g_Res[ROWS*DHd];

// =====================================================================
// Kernel 1: qkv = x @ Wqkv^T + bqkv, scattered into per-head Q/K/V.
// 128x128 tile, BK=16, 256 threads, 8x8 microtile (split 4+4 at +64).
// =====================================================================
__global__ __launch_bounds__(256) void k_gemm_qkv(const float* __restrict__ X,
                                                  const float* __restrict__ W,
                                                  const float* __restrict__ bias) {
    __shared__ float As[16][128];
    __shared__ float Bs[16][128];
    int tid = threadIdx.x;
    int tx = tid & 15, ty = tid >> 4;
    int m0 = blockIdx.y * 128, c0 = blockIdx.x * 128;
    float acc[8][8] = {};

    for (int k0 = 0; k0 < DIMV; k0 += 16) {
        #pragma unroll
        for (int it = 0; it < 2; it++) {
            int f = tid + it * 256;
            int r = f >> 2, kc = (f & 3) * 4;
            float4 av = *(const float4*)&X[(size_t)(m0 + r) * DIMV + k0 + kc];
            float4 bv = *(const float4*)&W[(size_t)(c0 + r) * DIMV + k0 + kc];
            As[kc+0][r] = av.x; As[kc+1][r] = av.y; As[kc+2][r] = av.z; As[kc+3][r] = av.w;
            Bs[kc+0][r] = bv.x; Bs[kc+1][r] = bv.y; Bs[kc+2][r] = bv.z; Bs[kc+3][r] = bv.w;
        }
        __syncthreads();
        #pragma unroll
        for (int k = 0; k < 16; k++) {
            float4 a0 = *(const float4*)&As[k][ty * 4];
            float4 a1 = *(const float4*)&As[k][ty * 4 + 64];
            float4 b0 = *(const float4*)&Bs[k][tx * 4];
            float4 b1 = *(const float4*)&Bs[k][tx * 4 + 64];
            float av[8] = {a0.x,a0.y,a0.z,a0.w,a1.x,a1.y,a1.z,a1.w};
            float bv[8] = {b0.x,b0.y,b0.z,b0.w,b1.x,b1.y,b1.z,b1.w};
            #pragma unroll
            for (int i = 0; i < 8; i++)
                #pragma unroll
                for (int j = 0; j < 8; j++)
                    acc[i][j] += av[i] * bv[j];
        }
        __syncthreads();
    }
    #pragma unroll
    for (int ih = 0; ih < 2; ih++) {
        #pragma unroll
        for (int i = 0; i < 4; i++) {
            int m = m0 + ih * 64 + ty * 4 + i;
            int b = m >> 10, n = m & 1023;
            #pragma unroll
            for (int jh = 0; jh < 2; jh++) {
                int c = c0 + jh * 64 + tx * 4;
                float4 v;
                v.x = acc[ih*4+i][jh*4+0] + bias[c+0];
                v.y = acc[ih*4+i][jh*4+1] + bias[c+1];
                v.z = acc[ih*4+i][jh*4+2] + bias[c+2];
                v.w = acc[ih*4+i][jh*4+3] + bias[c+3];
                int part = c >> 10;
                int hc = c & 1023;
                int h = hc >> 6, dh = hc & 63;
                float* dst = (part == 0) ? g_Q : ((part == 1) ? g_K : g_V);
                *(float4*)&dst[((size_t)((b * HH + h) * NN + n)) * DHd + dh] = v;
            }
        }
    }
}

// =====================================================================
// Kernel 2: QR[row][t] = Q[row] . rel_k_emb[t]
// =====================================================================
__global__ void k_qr(const float* __restrict__ relk) {
    __shared__ float sQ[32][65];
    int tid = threadIdx.x;
    int row0 = blockIdx.x * 32;
    for (int e = tid; e < 32 * 64; e += 256) {
        int r = e >> 6, d = e & 63;
        sQ[r][d] = g_Q[(size_t)(row0 + r) * DHd + d];
    }
    __syncthreads();
    for (int task = tid; task < 32 * VOC; task += 256) {
        int r = task / VOC, t = task % VOC;
        const float* rk = &relk[t * DHd];
        float acc = 0.f;
        #pragma unroll
        for (int d = 0; d < 64; d++) acc += sQ[r][d] * __ldg(&rk[d]);
        g_QR[(size_t)(row0 + r) * VOC + t] = acc;
    }
}

// =====================================================================
// Kernel 3: S = SCALE*Q.K^T + QR gather.  128x128 tile, K=64 via BK=16.
// grid (8, 8, 64)
// =====================================================================
__global__ __launch_bounds__(256) void k_scores() {
    __shared__ float Qs[16][128];
    __shared__ float Ks[16][128];
    int tid = threadIdx.x;
    int tx = tid & 15, ty = tid >> 4;
    int bh = blockIdx.z;
    int i0 = blockIdx.y * 128, j0 = blockIdx.x * 128;
    size_t qbase = (size_t)(bh * NN + i0) * DHd;
    size_t kbase = (size_t)(bh * NN + j0) * DHd;
    float acc[8][8] = {};

    for (int k0 = 0; k0 < DHd; k0 += 16) {
        #pragma unroll
        for (int it = 0; it < 2; it++) {
            int f = tid + it * 256;
            int r = f >> 2, kc = (f & 3) * 4;
            float4 qv = *(const float4*)&g_Q[qbase + (size_t)r * DHd + k0 + kc];
            float4 kv = *(const float4*)&g_K[kbase + (size_t)r * DHd + k0 + kc];
            Qs[kc+0][r] = qv.x; Qs[kc+1][r] = qv.y; Qs[kc+2][r] = qv.z; Qs[kc+3][r] = qv.w;
            Ks[kc+0][r] = kv.x; Ks[kc+1][r] = kv.y; Ks[kc+2][r] = kv.z; Ks[kc+3][r] = kv.w;
        }
        __syncthreads();
        #pragma unroll
        for (int k = 0; k < 16; k++) {
            float4 a0 = *(const float4*)&Qs[k][ty * 4];
            float4 a1 = *(const float4*)&Qs[k][ty * 4 + 64];
            float4 b0 = *(const float4*)&Ks[k][tx * 4];
            float4 b1 = *(const float4*)&Ks[k][tx * 4 + 64];
            float av[8] = {a0.x,a0.y,a0.z,a0.w,a1.x,a1.y,a1.z,a1.w};
            float bv[8] = {b0.x,b0.y,b0.z,b0.w,b1.x,b1.y,b1.z,b1.w};
            #pragma unroll
            for (int i = 0; i < 8; i++)
                #pragma unroll
                for (int j = 0; j < 8; j++)
                    acc[i][j] += av[i] * bv[j];
        }
        __syncthreads();
    }
    #pragma unroll
    for (int ih = 0; ih < 2; ih++) {
        #pragma unroll
        for (int i = 0; i < 4; i++) {
            int ii = i0 + ih * 64 + ty * 4 + i;
            const float* qr = &g_QR[(size_t)(bh * NN + ii) * VOC];
            size_t sbase = ((size_t)(bh * NN + ii)) * NN;
            #pragma unroll
            for (int jh = 0; jh < 2; jh++) {
                int jj0 = j0 + jh * 64 + tx * 4;
                float4 v;
                #pragma unroll
                for (int j = 0; j < 4; j++) {
                    int jj = jj0 + j;
                    int d = ii - jj;
                    d = d < -MAXREL ? -MAXREL : (d > MAXREL ? MAXREL : d);
                    ((float*)&v)[j] = acc[ih*4+i][jh*4+j] * SCALEv + qr[d + MAXREL];
                }
                *(float4*)&g_S[sbase + jj0] = v;
            }
        }
    }
}

// float -> order-preserving uint key
__device__ __forceinline__ unsigned ftokey(float f) {
    unsigned u = __float_as_uint(f);
    return (u & 0x80000000u) ? ~u : (u | 0x80000000u);
}

// =====================================================================
// Kernel 4 (fused): radix-select exact top-256 threshold + masked softmax
// + deterministic compaction + rel_v bucket trick -> ARel.
// One block (256 threads) per score row.
// =====================================================================
__global__ void k_select(const float* __restrict__ relv) {
    __shared__ float sbuf[1024];
    __shared__ int   hist[256];
    __shared__ int   scanA[256];
    __shared__ float redA[256];
    __shared__ float redB[256];
    __shared__ float rbin[VOC];
    __shared__ unsigned sh_selb;
    __shared__ int      sh_rem;

    int row = blockIdx.x;
    int tid = threadIdx.x;
    int i = row & (NN - 1);
    const float* src = &g_S[(size_t)row * NN];

    float lv[4]; unsigned kv[4];
    #pragma unroll
    for (int r = 0; r < 4; r++) {
        int j = tid * 4 + r;
        lv[r] = src[j];
        kv[r] = ftokey(lv[r]);
    }

    // row max (block tree reduce)
    float m = fmaxf(fmaxf(lv[0], lv[1]), fmaxf(lv[2], lv[3]));
    redA[tid] = m;
    __syncthreads();
    #pragma unroll
    for (int s = 128; s > 0; s >>= 1) {
        if (tid < s) redA[tid] = fmaxf(redA[tid], redA[tid + s]);
        __syncthreads();
    }
    float rmax = redA[0];
    __syncthreads();

    // radix select: exact key of the 256th largest
    unsigned prefix = 0;
    int need = TOPKv;
    #pragma unroll
    for (int round = 3; round >= 0; round--) {
        hist[tid] = 0;
        __syncthreads();
        unsigned mask = (round == 3) ? 0u : (0xFFFFFFFFu << ((round + 1) * 8));
        #pragma unroll
        for (int r = 0; r < 4; r++) {
            if ((kv[r] & mask) == prefix)
                atomicAdd(&hist[(kv[r] >> (round * 8)) & 255], 1);
        }
        __syncthreads();
        scanA[tid] = hist[tid];
        __syncthreads();
        // inclusive suffix sum: scanA[b] = count of bins >= b
        #pragma unroll
        for (int off = 1; off < 256; off <<= 1) {
            int v = (tid + off < 256) ? scanA[tid + off] : 0;
            __syncthreads();
            scanA[tid] += v;
            __syncthreads();
        }
        int Sb = scanA[tid];
        int Sb1 = (tid == 255) ? 0 : scanA[tid + 1];
        if (Sb >= need && Sb1 < need) { sh_selb = (unsigned)tid; sh_rem = Sb1; }
        __syncthreads();
        prefix |= sh_selb << (round * 8);
        need -= sh_rem;
        __syncthreads();
    }
    unsigned thrkey = prefix;

    // masked exp; marker -1 for masked-out
    float lsum = 0.f;
    #pragma unroll
    for (int r = 0; r < 4; r++) {
        int j = tid * 4 + r;
        float e;
        if (kv[r] >= thrkey) { e = __expf(lv[r] - rmax); lsum += e; }
        else e = -1.0f;
        sbuf[j] = e;
    }
    redA[tid] = lsum;
    __syncthreads();
    #pragma unroll
    for (int s = 128; s > 0; s >>= 1) {
        if (tid < s) redA[tid] += redA[tid + s];
        __syncthreads();
    }
    float inv = 1.0f / redA[0];
    __syncthreads();

    // rel_v buckets: t in 1..127 single element j = i+64-t; t=0 / t=128 tails
    if (tid >= 1 && tid < 128) {
        int j = i + MAXREL - tid;
        float v = 0.f;
        if (j >= 0 && j < NN) {
            float e = sbuf[j];
            if (e >= 0.f) v = e * inv;
        }
        rbin[tid] = v;
    }
    float s0 = 0.f, s128 = 0.f;
    #pragma unroll
    for (int r = 0; r < 4; r++) {
        int j = tid * 4 + r;
        float e = sbuf[j];
        float a = (e >= 0.f) ? e * inv : 0.f;
        if (j >= i + MAXREL) s0 += a;
        if (j <= i - MAXREL) s128 += a;
    }
    redA[tid] = s0; redB[tid] = s128;
    __syncthreads();
    #pragma unroll
    for (int s = 128; s > 0; s >>= 1) {
        if (tid < s) { redA[tid] += redA[tid + s]; redB[tid] += redB[tid + s]; }
        __syncthreads();
    }
    if (tid == 0) { rbin[0] = redA[0]; rbin[MAXREL * 2] = redB[0]; }
    __syncthreads();

    if (tid < DHd) {
        float acc = 0.f;
        #pragma unroll
        for (int t = 0; t < VOC; t++) acc += rbin[t] * __ldg(&relv[t * DHd + tid]);
        g_ARel[(size_t)row * DHd + tid] = acc;
    }

    // deterministic compaction (source order) into CI/CW
    int kc = 0;
    #pragma unroll
    for (int r = 0; r < 4; r++) if (sbuf[tid * 4 + r] >= 0.f) kc++;
    scanA[tid] = kc;
    __syncthreads();
    for (int off = 1; off < 256; off <<= 1) {
        int v = (tid >= off) ? scanA[tid - off] : 0;
        __syncthreads();
        scanA[tid] += v;
        __syncthreads();
    }
    int pos = scanA[tid] - kc;
    size_t cbase = (size_t)row * TOPKv;
    #pragma unroll
    for (int r = 0; r < 4; r++) {
        int j = tid * 4 + r;
        float e = sbuf[j];
        if (e >= 0.f) {
            if (pos < TOPKv) { g_CI[cbase + pos] = j; g_CW[cbase + pos] = e * inv; }
            pos++;
        }
    }
}

// =====================================================================
// Kernel 5: sparse apply v_out = attn @ v_in (+ARel on ord 0),
// Res (+)= sigmoid(alpha)*v_out. 512 threads, V half staged in smem.
// =====================================================================
__global__ __launch_bounds__(512) void k_apply(int ord, const float* __restrict__ alphas_raw) {
    extern __shared__ float smem[];
    float*  sV  = smem;                         // 1024*32 floats = 128 KB
    float2* sIW = (float2*)(smem + 1024 * 32);  // 16 warps * 256 = 32 KB

    const float* Vin  = (ord == 0) ? g_V  : ((ord == 1) ? g_VA : g_VB);
    float*       Vout = (ord == 0) ? g_VA : ((ord == 1) ? g_VB : g_VA);

    int bh = blockIdx.x >> 1;
    int d0 = (blockIdx.x & 1) * 32;
    int tid = threadIdx.x, wid = tid >> 5, lane = tid & 31;
    size_t vbase = (size_t)bh * NN * DHd;

    for (int e = tid; e < 1024 * 32; e += 512) {
        int r = e >> 5, c = e & 31;
        sV[e] = Vin[vbase + (size_t)r * DHd + d0 + c];
    }
    __syncthreads();

    int h = bh & (HH - 1);
    float araw = alphas_raw[ord * HH + h];
    float alpha = 1.0f / (1.0f + __expf(-araw));
    float2* myIW = sIW + wid * 256;

    for (int i = wid; i < NN; i += 16) {
        int row = bh * NN + i;
        const int*   ci = &g_CI[(size_t)row * TOPKv];
        const float* cw = &g_CW[(size_t)row * TOPKv];
        #pragma unroll
        for (int q = 0; q < 8; q++) {
            int p = q * 32 + lane;
            myIW[p] = make_float2(cw[p], __int_as_float(ci[p]));
        }
        __syncwarp();
        float a0 = 0.f, a1 = 0.f, a2 = 0.f, a3 = 0.f;
        #pragma unroll 4
        for (int p = 0; p < TOPKv; p += 4) {
            float2 w0 = myIW[p+0], w1 = myIW[p+1], w2 = myIW[p+2], w3 = myIW[p+3];
            a0 += w0.x * sV[__float_as_int(w0.y) * 32 + lane];
            a1 += w1.x * sV[__float_as_int(w1.y) * 32 + lane];
            a2 += w2.x * sV[__float_as_int(w2.y) * 32 + lane];
            a3 += w3.x * sV[__float_as_int(w3.y) * 32 + lane];
        }
        float acc = (a0 + a1) + (a2 + a3);
        __syncwarp();
        size_t oidx = (size_t)row * DHd + d0 + lane;
        if (ord == 0) acc += g_ARel[oidx];
        Vout[oidx] = acc;
        float rv = alpha * acc;
        if (ord == 0) g_Res[oidx] = rv;
        else          g_Res[oidx] += rv;
    }
}

// =====================================================================
// Kernel 6: out = res_flat @ Wout^T + bout.  128x128 tile, 8x8 micro.
// =====================================================================
__global__ __launch_bounds__(256) void k_gemm_out(const float* __restrict__ W,
                                                  const float* __restrict__ bias,
                                                  float* __restrict__ out) {
    __shared__ float As[16][128];
    __shared__ float Bs[16][128];
    int tid = threadIdx.x;
    int tx = tid & 15, ty = tid >> 4;
    int m0 = blockIdx.y * 128, o0 = blockIdx.x * 128;
    float acc[8][8] = {};

    for (int k0 = 0; k0 < DIMV; k0 += 16) {
        #pragma unroll
        for (int it = 0; it < 2; it++) {
            int f = tid + it * 256;
            int r = f >> 2, kc = (f & 3) * 4;
            int k = k0 + kc;
            int m = m0 + r;
            int b = m >> 10, n = m & 1023;
            int hh = k >> 6, dh = k & 63;
            float4 av = *(const float4*)&g_Res[((size_t)((b * HH + hh) * NN + n)) * DHd + dh];
            float4 bv = *(const float4*)&W[(size_t)(o0 + r) * DIMV + k];
            As[kc+0][r] = av.x; As[kc+1][r] = av.y; As[kc+2][r] = av.z; As[kc+3][r] = av.w;
            Bs[kc+0][r] = bv.x; Bs[kc+1][r] = bv.y; Bs[kc+2][r] = bv.z; Bs[kc+3][r] = bv.w;
        }
        __syncthreads();
        #pragma unroll
        for (int k = 0; k < 16; k++) {
            float4 a0 = *(const float4*)&As[k][ty * 4];
            float4 a1 = *(const float4*)&As[k][ty * 4 + 64];
            float4 b0 = *(const float4*)&Bs[k][tx * 4];
            float4 b1 = *(const float4*)&Bs[k][tx * 4 + 64];
            float av[8] = {a0.x,a0.y,a0.z,a0.w,a1.x,a1.y,a1.z,a1.w};
            float bv[8] = {b0.x,b0.y,b0.z,b0.w,b1.x,b1.y,b1.z,b1.w};
            #pragma unroll
            for (int i = 0; i < 8; i++)
                #pragma unroll
                for (int j = 0; j < 8; j++)
                    acc[i][j] += av[i] * bv[j];
        }
        __syncthreads();
    }
    #pragma unroll
    for (int ih = 0; ih < 2; ih++) {
        #pragma unroll
        for (int i = 0; i < 4; i++) {
            int m = m0 + ih * 64 + ty * 4 + i;
            #pragma unroll
            for (int jh = 0; jh < 2; jh++) {
                int o = o0 + jh * 64 + tx * 4;
                float4 v;
                v.x = acc[ih*4+i][jh*4+0] + bias[o+0];
                v.y = acc[ih*4+i][jh*4+1] + bias[o+1];
                v.z = acc[ih*4+i][jh*4+2] + bias[o+2];
                v.w = acc[ih*4+i][jh*4+3] + bias[o+3];
                *(float4*)&out[(size_t)m * DIMV + o] = v;
            }
        }
    }
}

// =====================================================================
extern "C" void kernel_launch(void* const* d_in, const int* in_sizes, int n_in,
                              void* d_out, int out_size) {
    const float* x      = (const float*)d_in[0];
    const float* Wqkv   = (const float*)d_in[1];
    const float* bqkv   = (const float*)d_in[2];
    const float* Wout   = (const float*)d_in[3];
    const float* bout   = (const float*)d_in[4];
    const float* relk   = (const float*)d_in[5];
    const float* relv   = (const float*)d_in[6];
    const float* alphas = (const float*)d_in[7];
    float* out = (float*)d_out;

    k_gemm_qkv<<<dim3(24, 32), 256>>>(x, Wqkv, bqkv);
    k_qr<<<ROWS / 32, 256>>>(relk);
    k_scores<<<dim3(8, 8, BHH), 256>>>();
    k_select<<<ROWS, 256>>>(relv);

    cudaFuncSetAttribute(k_apply, cudaFuncAttributeMaxDynamicSharedMemorySize, 163840);
    k_apply<<<BHH * 2, 512, 163840>>>(0, alphas);
    k_apply<<<BHH * 2, 512, 163840>>>(1, alphas);
    k_apply<<<BHH * 2, 512, 163840>>>(2, alphas);

    k_gemm_out<<<dim3(8, 32), 256>>>(Wout, bout, out);
}

// round 3
// speedup vs baseline: 1.5366x; 1.0219x over previous
#include <cuda_runtime.h>

// ---------------- problem constants ----------------
#define Bb 4
#define NN 1024
#define DIMV 1024
#define HH 16
#define DHd 64
#define VOC 129            // 2*MAXREL+1
#define MAXREL 64
#define TOPKv 256
#define BHH (Bb*HH)        // 64
#define ROWS (BHH*NN)      // 65536
#define SCALEv 0.125f      // DH^-0.5

typedef unsigned long long u64;

// ---------------- device scratch (no allocs allowed) ----------------
__device__ float g_Q[ROWS*DHd];
__device__ float g_K[ROWS*DHd];
__device__ float g_V[ROWS*DHd];
__device__ float g_S[(size_t)ROWS*NN];        // 256 MB scores
__device__ float g_QR[ROWS*VOC];              // q @ rel_k_emb^T
__device__ float g_CW[ROWS*TOPKv];            // compact attn weights
__device__ int   g_CI[ROWS*TOPKv];            // compact attn column indices
__device__ float g_ARel[ROWS*DHd];            // attn @ rel_v
__device__ float g_VA[ROWS*DHd];
__device__ float g_VB[ROWS*DHd];
__device__ float g_Res[ROWS*DHd];

// ---------------- packed f32x2 helpers ----------------
__device__ __forceinline__ void ffma2(u64 &d, u64 a, u64 b) {
    asm("fma.rn.f32x2 %0, %1, %2, %0;" : "+l"(d) : "l"(a), "l"(b));
}
__device__ __forceinline__ u64 dup2(float x) {
    u64 r; asm("mov.b64 %0, {%1, %1};" : "=l"(r) : "f"(x)); return r;
}
__device__ __forceinline__ float2 unpack2(u64 v) {
    float2 f; asm("mov.b64 {%0, %1}, %2;" : "=f"(f.x), "=f"(f.y) : "l"(v)); return f;
}

// =====================================================================
// Kernel 1: qkv = x @ Wqkv^T + bqkv, scattered into per-head Q/K/V.
// 128x128 tile, BK=16, 256 threads, 8x8 microtile, FFMA2 inner.
// =====================================================================
__global__ __launch_bounds__(256) void k_gemm_qkv(const float* __restrict__ X,
                                                  const float* __restrict__ W,
                                                  const float* __restrict__ bias) {
    __shared__ float As[16][128];
    __shared__ float Bs[16][128];
    int tid = threadIdx.x;
    int tx = tid & 15, ty = tid >> 4;
    int m0 = blockIdx.y * 128, c0 = blockIdx.x * 128;
    u64 acc2[8][4] = {};

    for (int k0 = 0; k0 < DIMV; k0 += 16) {
        #pragma unroll
        for (int it = 0; it < 2; it++) {
            int f = tid + it * 256;
            int r = f >> 2, kc = (f & 3) * 4;
            float4 av = *(const float4*)&X[(size_t)(m0 + r) * DIMV + k0 + kc];
            float4 bv = *(const float4*)&W[(size_t)(c0 + r) * DIMV + k0 + kc];
            As[kc+0][r] = av.x; As[kc+1][r] = av.y; As[kc+2][r] = av.z; As[kc+3][r] = av.w;
            Bs[kc+0][r] = bv.x; Bs[kc+1][r] = bv.y; Bs[kc+2][r] = bv.z; Bs[kc+3][r] = bv.w;
        }
        __syncthreads();
        #pragma unroll
        for (int k = 0; k < 16; k++) {
            float4 a0 = *(const float4*)&As[k][ty * 4];
            float4 a1 = *(const float4*)&As[k][ty * 4 + 64];
            ulonglong2 b0 = *(const ulonglong2*)&Bs[k][tx * 4];
            ulonglong2 b1 = *(const ulonglong2*)&Bs[k][tx * 4 + 64];
            u64 ad[8];
            ad[0]=dup2(a0.x); ad[1]=dup2(a0.y); ad[2]=dup2(a0.z); ad[3]=dup2(a0.w);
            ad[4]=dup2(a1.x); ad[5]=dup2(a1.y); ad[6]=dup2(a1.z); ad[7]=dup2(a1.w);
            #pragma unroll
            for (int i = 0; i < 8; i++) {
                ffma2(acc2[i][0], ad[i], b0.x);
                ffma2(acc2[i][1], ad[i], b0.y);
                ffma2(acc2[i][2], ad[i], b1.x);
                ffma2(acc2[i][3], ad[i], b1.y);
            }
        }
        __syncthreads();
    }
    #pragma unroll
    for (int ih = 0; ih < 2; ih++) {
        #pragma unroll
        for (int i = 0; i < 4; i++) {
            int m = m0 + ih * 64 + ty * 4 + i;
            int b = m >> 10, n = m & 1023;
            #pragma unroll
            for (int jh = 0; jh < 2; jh++) {
                int c = c0 + jh * 64 + tx * 4;
                float2 lo = unpack2(acc2[ih*4+i][jh*2+0]);
                float2 hi = unpack2(acc2[ih*4+i][jh*2+1]);
                float4 v;
                v.x = lo.x + bias[c+0];
                v.y = lo.y + bias[c+1];
                v.z = hi.x + bias[c+2];
                v.w = hi.y + bias[c+3];
                int part = c >> 10;
                int hc = c & 1023;
                int h = hc >> 6, dh = hc & 63;
                float* dst = (part == 0) ? g_Q : ((part == 1) ? g_K : g_V);
                *(float4*)&dst[((size_t)((b * HH + h) * NN + n)) * DHd + dh] = v;
            }
        }
    }
}

// =====================================================================
// Kernel 2: QR[row][t] = Q[row] . rel_k_emb[t]
// =====================================================================
__global__ void k_qr(const float* __restrict__ relk) {
    __shared__ float sQ[32][65];
    int tid = threadIdx.x;
    int row0 = blockIdx.x * 32;
    for (int e = tid; e < 32 * 64; e += 256) {
        int r = e >> 6, d = e & 63;
        sQ[r][d] = g_Q[(size_t)(row0 + r) * DHd + d];
    }
    __syncthreads();
    for (int task = tid; task < 32 * VOC; task += 256) {
        int r = task / VOC, t = task % VOC;
        const float* rk = &relk[t * DHd];
        float acc = 0.f;
        #pragma unroll
        for (int d = 0; d < 64; d++) acc += sQ[r][d] * __ldg(&rk[d]);
        g_QR[(size_t)(row0 + r) * VOC + t] = acc;
    }
}

// =====================================================================
// Kernel 3: S = SCALE*Q.K^T + QR gather.  128x128 tile, FFMA2 inner.
// grid (8, 8, 64)
// =====================================================================
__global__ __launch_bounds__(256) void k_scores() {
    __shared__ float Qs[16][128];
    __shared__ float Ks[16][128];
    int tid = threadIdx.x;
    int tx = tid & 15, ty = tid >> 4;
    int bh = blockIdx.z;
    int i0 = blockIdx.y * 128, j0 = blockIdx.x * 128;
    size_t qbase = (size_t)(bh * NN + i0) * DHd;
    size_t kbase = (size_t)(bh * NN + j0) * DHd;
    u64 acc2[8][4] = {};

    for (int k0 = 0; k0 < DHd; k0 += 16) {
        #pragma unroll
        for (int it = 0; it < 2; it++) {
            int f = tid + it * 256;
            int r = f >> 2, kc = (f & 3) * 4;
            float4 qv = *(const float4*)&g_Q[qbase + (size_t)r * DHd + k0 + kc];
            float4 kv = *(const float4*)&g_K[kbase + (size_t)r * DHd + k0 + kc];
            Qs[kc+0][r] = qv.x; Qs[kc+1][r] = qv.y; Qs[kc+2][r] = qv.z; Qs[kc+3][r] = qv.w;
            Ks[kc+0][r] = kv.x; Ks[kc+1][r] = kv.y; Ks[kc+2][r] = kv.z; Ks[kc+3][r] = kv.w;
        }
        __syncthreads();
        #pragma unroll
        for (int k = 0; k < 16; k++) {
            float4 a0 = *(const float4*)&Qs[k][ty * 4];
            float4 a1 = *(const float4*)&Qs[k][ty * 4 + 64];
            ulonglong2 b0 = *(const ulonglong2*)&Ks[k][tx * 4];
            ulonglong2 b1 = *(const ulonglong2*)&Ks[k][tx * 4 + 64];
            u64 ad[8];
            ad[0]=dup2(a0.x); ad[1]=dup2(a0.y); ad[2]=dup2(a0.z); ad[3]=dup2(a0.w);
            ad[4]=dup2(a1.x); ad[5]=dup2(a1.y); ad[6]=dup2(a1.z); ad[7]=dup2(a1.w);
            #pragma unroll
            for (int i = 0; i < 8; i++) {
                ffma2(acc2[i][0], ad[i], b0.x);
                ffma2(acc2[i][1], ad[i], b0.y);
                ffma2(acc2[i][2], ad[i], b1.x);
                ffma2(acc2[i][3], ad[i], b1.y);
            }
        }
        __syncthreads();
    }
    #pragma unroll
    for (int ih = 0; ih < 2; ih++) {
        #pragma unroll
        for (int i = 0; i < 4; i++) {
            int ii = i0 + ih * 64 + ty * 4 + i;
            const float* qr = &g_QR[(size_t)(bh * NN + ii) * VOC];
            size_t sbase = ((size_t)(bh * NN + ii)) * NN;
            #pragma unroll
            for (int jh = 0; jh < 2; jh++) {
                int jj0 = j0 + jh * 64 + tx * 4;
                float2 lo = unpack2(acc2[ih*4+i][jh*2+0]);
                float2 hi = unpack2(acc2[ih*4+i][jh*2+1]);
                float accv[4] = {lo.x, lo.y, hi.x, hi.y};
                float4 v;
                #pragma unroll
                for (int j = 0; j < 4; j++) {
                    int jj = jj0 + j;
                    int d = ii - jj;
                    d = d < -MAXREL ? -MAXREL : (d > MAXREL ? MAXREL : d);
                    ((float*)&v)[j] = accv[j] * SCALEv + qr[d + MAXREL];
                }
                *(float4*)&g_S[sbase + jj0] = v;
            }
        }
    }
}

// float -> order-preserving uint key
__device__ __forceinline__ unsigned ftokey(float f) {
    unsigned u = __float_as_uint(f);
    return (u & 0x80000000u) ? ~u : (u | 0x80000000u);
}

// =====================================================================
// Kernel 4 (fused): radix-select exact top-256 threshold + masked softmax
// + deterministic compaction + rel_v bucket trick -> ARel.
// Warp-shuffle scans/reductions; ~23 block barriers total.
// One block (256 threads) per score row.
// =====================================================================
__global__ __launch_bounds__(256) void k_select(const float* __restrict__ relv) {
    __shared__ float sbuf[1024];
    __shared__ int   hist[256];
    __shared__ float wredf[8];
    __shared__ float wredf2[8];
    __shared__ int   wredi[8];
    __shared__ float rbin[VOC];
    __shared__ unsigned sh_selb;
    __shared__ int      sh_rem;

    int row = blockIdx.x;
    int tid = threadIdx.x;
    int lane = tid & 31, wid = tid >> 5;
    int i = row & (NN - 1);
    const float* src = &g_S[(size_t)row * NN];

    float lv[4]; unsigned kv[4];
    #pragma unroll
    for (int r = 0; r < 4; r++) {
        int j = tid * 4 + r;
        lv[r] = src[j];
        kv[r] = ftokey(lv[r]);
    }

    // ---- row max: warp reduce + cross-warp via smem ----
    float m = fmaxf(fmaxf(lv[0], lv[1]), fmaxf(lv[2], lv[3]));
    #pragma unroll
    for (int off = 16; off > 0; off >>= 1)
        m = fmaxf(m, __shfl_xor_sync(0xffffffffu, m, off));
    if (lane == 0) wredf[wid] = m;
    __syncthreads();
    float rmax = wredf[0];
    #pragma unroll
    for (int w = 1; w < 8; w++) rmax = fmaxf(rmax, wredf[w]);

    // ---- radix select: exact key of the 256th largest ----
    unsigned prefix = 0;
    int need = TOPKv;
    for (int round = 3; round >= 0; round--) {
        hist[tid] = 0;
        __syncthreads();
        unsigned mask = (round == 3) ? 0u : (0xFFFFFFFFu << ((round + 1) * 8));
        #pragma unroll
        for (int r = 0; r < 4; r++) {
            if ((kv[r] & mask) == prefix)
                atomicAdd(&hist[(kv[r] >> (round * 8)) & 255], 1);
        }
        __syncthreads();
        int h = hist[tid];
        int s = h;          // inclusive suffix within warp
        #pragma unroll
        for (int off = 1; off < 32; off <<= 1) {
            int v = __shfl_down_sync(0xffffffffu, s, off);
            if (lane + off < 32) s += v;
        }
        int wtot = __shfl_sync(0xffffffffu, s, 0);
        if (lane == 0) wredi[wid] = wtot;
        __syncthreads();
        int tail = 0;
        #pragma unroll
        for (int w = 0; w < 8; w++) if (w > wid) tail += wredi[w];
        int Sb = s + tail;          // count of keys >= bin tid
        int Sb1 = Sb - h;           // count of keys >= bin tid+1
        if (Sb >= need && Sb1 < need) { sh_selb = (unsigned)tid; sh_rem = Sb1; }
        __syncthreads();
        prefix |= sh_selb << (round * 8);
        need -= sh_rem;
        __syncthreads();
    }
    unsigned thrkey = prefix;

    // ---- masked exp + block sum ----
    float lsum = 0.f;
    #pragma unroll
    for (int r = 0; r < 4; r++) {
        int j = tid * 4 + r;
        float e;
        if (kv[r] >= thrkey) { e = __expf(lv[r] - rmax); lsum += e; }
        else e = -1.0f;
        sbuf[j] = e;
    }
    float ws = lsum;
    #pragma unroll
    for (int off = 16; off > 0; off >>= 1)
        ws += __shfl_xor_sync(0xffffffffu, ws, off);
    if (lane == 0) wredf[wid] = ws;
    __syncthreads();
    float tot = 0.f;
    #pragma unroll
    for (int w = 0; w < 8; w++) tot += wredf[w];
    float inv = 1.0f / tot;

    // ---- rel_v buckets ----
    if (tid >= 1 && tid < 128) {
        int j = i + MAXREL - tid;
        float v = 0.f;
        if (j >= 0 && j < NN) {
            float e = sbuf[j];
            if (e >= 0.f) v = e * inv;
        }
        rbin[tid] = v;
    }
    float s0 = 0.f, s128 = 0.f;
    #pragma unroll
    for (int r = 0; r < 4; r++) {
        int j = tid * 4 + r;
        float e = sbuf[j];
        float a = (e >= 0.f) ? e * inv : 0.f;
        if (j >= i + MAXREL) s0 += a;
        if (j <= i - MAXREL) s128 += a;
    }
    #pragma unroll
    for (int off = 16; off > 0; off >>= 1) {
        s0   += __shfl_xor_sync(0xffffffffu, s0, off);
        s128 += __shfl_xor_sync(0xffffffffu, s128, off);
    }
    __syncthreads();   // wredf free again
    if (lane == 0) { wredf[wid] = s0; wredf2[wid] = s128; }
    __syncthreads();
    if (tid == 0) {
        float a = 0.f, b = 0.f;
        #pragma unroll
        for (int w = 0; w < 8; w++) { a += wredf[w]; b += wredf2[w]; }
        rbin[0] = a; rbin[MAXREL * 2] = b;
    }
    __syncthreads();

    if (tid < DHd) {
        float acc = 0.f;
        #pragma unroll
        for (int t = 0; t < VOC; t++) acc += rbin[t] * __ldg(&relv[t * DHd + tid]);
        g_ARel[(size_t)row * DHd + tid] = acc;
    }

    // ---- deterministic compaction (source order) ----
    int kc = 0;
    #pragma unroll
    for (int r = 0; r < 4; r++) if (sbuf[tid * 4 + r] >= 0.f) kc++;
    int p = kc;        // inclusive prefix within warp
    #pragma unroll
    for (int off = 1; off < 32; off <<= 1) {
        int v = __shfl_up_sync(0xffffffffu, p, off);
        if (lane >= off) p += v;
    }
    if (lane == 31) wredi[wid] = p;
    __syncthreads();
    int base = 0;
    #pragma unroll
    for (int w = 0; w < 8; w++) if (w < wid) base += wredi[w];
    int pos = base + p - kc;
    size_t cbase = (size_t)row * TOPKv;
    #pragma unroll
    for (int r = 0; r < 4; r++) {
        int j = tid * 4 + r;
        float e = sbuf[j];
        if (e >= 0.f) {
            if (pos < TOPKv) { g_CI[cbase + pos] = j; g_CW[cbase + pos] = e * inv; }
            pos++;
        }
    }
}

// =====================================================================
// Kernel 5: sparse apply v_out = attn @ v_in (+ARel on ord 0),
// Res (+)= sigmoid(alpha)*v_out. 512 threads, V half staged in smem.
// =====================================================================
__global__ __launch_bounds__(512) void k_apply(int ord, const float* __restrict__ alphas_raw) {
    extern __shared__ float smem[];
    float*  sV  = smem;                         // 1024*32 floats = 128 KB
    float2* sIW = (float2*)(smem + 1024 * 32);  // 16 warps * 256 = 32 KB

    const float* Vin  = (ord == 0) ? g_V  : ((ord == 1) ? g_VA : g_VB);
    float*       Vout = (ord == 0) ? g_VA : ((ord == 1) ? g_VB : g_VA);

    int bh = blockIdx.x >> 1;
    int d0 = (blockIdx.x & 1) * 32;
    int tid = threadIdx.x, wid = tid >> 5, lane = tid & 31;
    size_t vbase = (size_t)bh * NN * DHd;

    for (int e = tid; e < 1024 * 32; e += 512) {
        int r = e >> 5, c = e & 31;
        sV[e] = Vin[vbase + (size_t)r * DHd + d0 + c];
    }
    __syncthreads();

    int h = bh & (HH - 1);
    float araw = alphas_raw[ord * HH + h];
    float alpha = 1.0f / (1.0f + __expf(-araw));
    float2* myIW = sIW + wid * 256;

    for (int i = wid; i < NN; i += 16) {
        int row = bh * NN + i;
        const int*   ci = &g_CI[(size_t)row * TOPKv];
        const float* cw = &g_CW[(size_t)row * TOPKv];
        #pragma unroll
        for (int q = 0; q < 8; q++) {
            int p = q * 32 + lane;
            myIW[p] = make_float2(cw[p], __int_as_float(ci[p]));
        }
        __syncwarp();
        float a0 = 0.f, a1 = 0.f, a2 = 0.f, a3 = 0.f;
        #pragma unroll 4
        for (int p = 0; p < TOPKv; p += 4) {
            float2 w0 = myIW[p+0], w1 = myIW[p+1], w2 = myIW[p+2], w3 = myIW[p+3];
            a0 += w0.x * sV[__float_as_int(w0.y) * 32 + lane];
            a1 += w1.x * sV[__float_as_int(w1.y) * 32 + lane];
            a2 += w2.x * sV[__float_as_int(w2.y) * 32 + lane];
            a3 += w3.x * sV[__float_as_int(w3.y) * 32 + lane];
        }
        float acc = (a0 + a1) + (a2 + a3);
        __syncwarp();
        size_t oidx = (size_t)row * DHd + d0 + lane;
        if (ord == 0) acc += g_ARel[oidx];
        Vout[oidx] = acc;
        float rv = alpha * acc;
        if (ord == 0) g_Res[oidx] = rv;
        else          g_Res[oidx] += rv;
    }
}

// =====================================================================
// Kernel 6: out = res_flat @ Wout^T + bout.  128x128 tile, FFMA2 inner.
// =====================================================================
__global__ __launch_bounds__(256) void k_gemm_out(const float* __restrict__ W,
                                                  const float* __restrict__ bias,
                                                  float* __restrict__ out) {
    __shared__ float As[16][128];
    __shared__ float Bs[16][128];
    int tid = threadIdx.x;
    int tx = tid & 15, ty = tid >> 4;
    int m0 = blockIdx.y * 128, o0 = blockIdx.x * 128;
    u64 acc2[8][4] = {};

    for (int k0 = 0; k0 < DIMV; k0 += 16) {
        #pragma unroll
        for (int it = 0; it < 2; it++) {
            int f = tid + it * 256;
            int r = f >> 2, kc = (f & 3) * 4;
            int k = k0 + kc;
            int m = m0 + r;
            int b = m >> 10, n = m & 1023;
            int hh = k >> 6, dh = k & 63;
            float4 av = *(const float4*)&g_Res[((size_t)((b * HH + hh) * NN + n)) * DHd + dh];
            float4 bv = *(const float4*)&W[(size_t)(o0 + r) * DIMV + k];
            As[kc+0][r] = av.x; As[kc+1][r] = av.y; As[kc+2][r] = av.z; As[kc+3][r] = av.w;
            Bs[kc+0][r] = bv.x; Bs[kc+1][r] = bv.y; Bs[kc+2][r] = bv.z; Bs[kc+3][r] = bv.w;
        }
        __syncthreads();
        #pragma unroll
        for (int k = 0; k < 16; k++) {
            float4 a0 = *(const float4*)&As[k][ty * 4];
            float4 a1 = *(const float4*)&As[k][ty * 4 + 64];
            ulonglong2 b0 = *(const ulonglong2*)&Bs[k][tx * 4];
            ulonglong2 b1 = *(const ulonglong2*)&Bs[k][tx * 4 + 64];
            u64 ad[8];
            ad[0]=dup2(a0.x); ad[1]=dup2(a0.y); ad[2]=dup2(a0.z); ad[3]=dup2(a0.w);
            ad[4]=dup2(a1.x); ad[5]=dup2(a1.y); ad[6]=dup2(a1.z); ad[7]=dup2(a1.w);
            #pragma unroll
            for (int i = 0; i < 8; i++) {
                ffma2(acc2[i][0], ad[i], b0.x);
                ffma2(acc2[i][1], ad[i], b0.y);
                ffma2(acc2[i][2], ad[i], b1.x);
                ffma2(acc2[i][3], ad[i], b1.y);
            }
        }
        __syncthreads();
    }
    #pragma unroll
    for (int ih = 0; ih < 2; ih++) {
        #pragma unroll
        for (int i = 0; i < 4; i++) {
            int m = m0 + ih * 64 + ty * 4 + i;
            #pragma unroll
            for (int jh = 0; jh < 2; jh++) {
                int o = o0 + jh * 64 + tx * 4;
                float2 lo = unpack2(acc2[ih*4+i][jh*2+0]);
                float2 hi = unpack2(acc2[ih*4+i][jh*2+1]);
                float4 v;
                v.x = lo.x + bias[o+0];
                v.y = lo.y + bias[o+1];
                v.z = hi.x + bias[o+2];
                v.w = hi.y + bias[o+3];
                *(float4*)&out[(size_t)m * DIMV + o] = v;
            }
        }
    }
}

// =====================================================================
extern "C" void kernel_launch(void* const* d_in, const int* in_sizes, int n_in,
                              void* d_out, int out_size) {
    const float* x      = (const float*)d_in[0];
    const float* Wqkv   = (const float*)d_in[1];
    const float* bqkv   = (const float*)d_in[2];
    const float* Wout   = (const float*)d_in[3];
    const float* bout   = (const float*)d_in[4];
    const float* relk   = (const float*)d_in[5];
    const float* relv   = (const float*)d_in[6];
    const float* alphas = (const float*)d_in[7];
    float* out = (float*)d_out;

    k_gemm_qkv<<<dim3(24, 32), 256>>>(x, Wqkv, bqkv);
    k_qr<<<ROWS / 32, 256>>>(relk);
    k_scores<<<dim3(8, 8, BHH), 256>>>();
    k_select<<<ROWS, 256>>>(relv);

    cudaFuncSetAttribute(k_apply, cudaFuncAttributeMaxDynamicSharedMemorySize, 163840);
    k_apply<<<BHH * 2, 512, 163840>>>(0, alphas);
    k_apply<<<BHH * 2, 512, 163840>>>(1, alphas);
    k_apply<<<BHH * 2, 512, 163840>>>(2, alphas);

    k_gemm_out<<<dim3(8, 32), 256>>>(Wout, bout, out);
}